// round 8
// baseline (speedup 1.0000x reference)
#include <cuda_runtime.h>

#define Hh 128
#define Ww 128
#define HW 16384
#define Bb 4
#define Cin 64
#define Cout 64

// scratch (device globals — no allocation)
__device__ float g_om[4 * 27 * HW];     // offset/mask conv output
__device__ float g_conv[4 * 64 * HW];   // deform conv output (pre-BN)
__device__ float g_wt[576 * 64];        // transposed deform weights [ck][o]
__device__ float g_stats[128];          // [0:64) sum, [64:128) sumsq

// ---------------------------------------------------------------------------
__global__ void zero_stats_kernel() {
    if (threadIdx.x < 128) g_stats[threadIdx.x] = 0.f;
}

// ---------------------------------------------------------------------------
// One-time weight transpose: g_wt[(c*9+k)*64 + o] = wgt[o*576 + c*9 + k]
__global__ __launch_bounds__(256) void wt_transpose_kernel(
        const float* __restrict__ wgt) {
    int idx = blockIdx.x * 256 + threadIdx.x;   // 36864 total
    if (idx < 576 * 64) {
        int o  = idx / 576;
        int ck = idx % 576;
        g_wt[ck * 64 + o] = wgt[idx];
    }
}

// ---------------------------------------------------------------------------
// Offset/mask conv: om[b, oc, h, w] = sum_{c,tap} x[b,c,h+dy,w+dx] * ow[oc,c,tap] + ob[oc]
// Tile: 16(w) x 8(h), 128 threads. Weights staged in smem as [cl][tap][oc pad 28].
__global__ __launch_bounds__(128) void offset_conv_kernel(
        const float* __restrict__ x,
        const float* __restrict__ ow,
        const float* __restrict__ ob) {
    __shared__ __align__(16) float sw[32 * 9 * 28];   // 32.25 KB
    const int tx = threadIdx.x & 15;
    const int ty = threadIdx.x >> 4;
    const int w = blockIdx.x * 16 + tx;
    const int h = blockIdx.y * 8 + ty;
    const int b = blockIdx.z;

    float acc[28];
#pragma unroll
    for (int i = 0; i < 28; i++) acc[i] = 0.f;

    for (int cc = 0; cc < 64; cc += 32) {
        __syncthreads();
        // zero the pad column (oc = 27) so float4 weight reads are clean
        for (int r = threadIdx.x; r < 288; r += 128) sw[r * 28 + 27] = 0.f;
        // stage weights: global ow[oc*576 + (cc+cl)*9 + tap]; coalesced over r
        for (int j = threadIdx.x; j < 27 * 288; j += 128) {
            int oc = j / 288;
            int r  = j - oc * 288;               // cl*9 + tap
            sw[r * 28 + oc] = ow[oc * 576 + cc * 9 + r];
        }
        __syncthreads();
        for (int cl = 0; cl < 32; cl++) {
            const float* xb = x + ((size_t)(b * 64 + cc + cl)) * HW;
            float xv[9];
#pragma unroll
            for (int ky = 0; ky < 3; ky++)
#pragma unroll
                for (int kx = 0; kx < 3; kx++) {
                    int yy = h - 1 + ky, xx = w - 1 + kx;
                    xv[ky * 3 + kx] =
                        ((unsigned)yy < 128u && (unsigned)xx < 128u) ? xb[yy * 128 + xx] : 0.f;
                }
#pragma unroll
            for (int tap = 0; tap < 9; tap++) {
                float v = xv[tap];
                const float4* wp = (const float4*)&sw[(cl * 9 + tap) * 28];
#pragma unroll
                for (int q = 0; q < 7; q++) {
                    float4 wv = wp[q];
                    acc[q * 4 + 0] += v * wv.x;
                    acc[q * 4 + 1] += v * wv.y;
                    acc[q * 4 + 2] += v * wv.z;
                    acc[q * 4 + 3] += v * wv.w;
                }
            }
        }
    }
    size_t base = (size_t)b * 27 * HW + h * 128 + w;
#pragma unroll
    for (int oc = 0; oc < 27; oc++)
        g_om[base + (size_t)oc * HW] = acc[oc] + ob[oc];
}

// ---------------------------------------------------------------------------
// Deformable conv as tiled GEMM (see prior rounds). Epilogue fuses BN stats.
__global__ __launch_bounds__(256) void deform_kernel(
        const float* __restrict__ x,
        const float* __restrict__ bias) {
    __shared__ int   s_y0[288], s_x0[288];
    __shared__ float s_fy[288], s_fx[288], s_m[288];
    __shared__ __align__(16) float Vs[72 * 32];   // 9 KB
    __shared__ __align__(16) float ws[72 * 64];   // 18 KB
    __shared__ float red_s[256], red_q[256];

    const int t  = threadIdx.x;
    const int b  = blockIdx.z;
    const int h  = blockIdx.y;
    const int w0 = blockIdx.x * 32;

    // phase 0: per-(tap, pixel) sampling coords + mask
    for (int idx = t; idx < 288; idx += 256) {
        int p = idx & 31, k = idx >> 5;
        size_t omb = (size_t)b * 27 * HW + h * 128 + (w0 + p);
        float dy = g_om[omb + (size_t)(2 * k) * HW];
        float dx = g_om[omb + (size_t)(2 * k + 1) * HW];
        float ml = g_om[omb + (size_t)(18 + k) * HW];
        float ys = (float)(h - 1 + k / 3) + dy;
        float xs = (float)(w0 + p - 1 + (k % 3)) + dx;
        float y0f = floorf(ys), x0f = floorf(xs);
        s_y0[idx] = (int)y0f;
        s_x0[idx] = (int)x0f;
        s_fy[idx] = ys - y0f;
        s_fx[idx] = xs - x0f;
        s_m[idx]  = 1.f / (1.f + expf(-ml));
    }
    __syncthreads();

    const int o  = t & 63;
    const int pg = t >> 6;
    float acc[8];
#pragma unroll
    for (int i = 0; i < 8; i++) acc[i] = 0.f;

    for (int c0 = 0; c0 < 64; c0 += 8) {
        // stage weights: straight float4 copy of g_wt rows [c0*9 .. c0*9+72)
        {
            const float4* src = (const float4*)(g_wt + (size_t)c0 * 9 * 64);
            float4* dst = (float4*)ws;
#pragma unroll
            for (int j = t; j < 72 * 64 / 4; j += 256) dst[j] = src[j];
        }
        // gather V[ckl][p]
        for (int i = t; i < 72 * 32; i += 256) {
            int p   = i & 31;
            int ckl = i >> 5;
            int c   = c0 + ckl / 9;
            int k   = ckl % 9;
            int ci  = k * 32 + p;
            int y0 = s_y0[ci], x0 = s_x0[ci];
            float fy = s_fy[ci], fx = s_fx[ci], m = s_m[ci];
            const float* xb = x + ((size_t)(b * 64 + c)) * HW;
            float v00 = ((unsigned)y0 < 128u && (unsigned)x0 < 128u) ? xb[y0 * 128 + x0] : 0.f;
            float v01 = ((unsigned)y0 < 128u && (unsigned)(x0 + 1) < 128u) ? xb[y0 * 128 + x0 + 1] : 0.f;
            float v10 = ((unsigned)(y0 + 1) < 128u && (unsigned)x0 < 128u) ? xb[(y0 + 1) * 128 + x0] : 0.f;
            float v11 = ((unsigned)(y0 + 1) < 128u && (unsigned)(x0 + 1) < 128u) ? xb[(y0 + 1) * 128 + x0 + 1] : 0.f;
            float top = v00 + fx * (v01 - v00);
            float bot = v10 + fx * (v11 - v10);
            Vs[ckl * 32 + p] = (top + fy * (bot - top)) * m;
        }
        __syncthreads();
        // GEMM: acc[p] += ws[ckl][o] * Vs[ckl][pg*8 + p]
#pragma unroll 8
        for (int ckl = 0; ckl < 72; ckl++) {
            float wv  = ws[ckl * 64 + o];
            float4 a  = *(const float4*)&Vs[ckl * 32 + pg * 8];
            float4 b4 = *(const float4*)&Vs[ckl * 32 + pg * 8 + 4];
            acc[0] += wv * a.x;  acc[1] += wv * a.y;
            acc[2] += wv * a.z;  acc[3] += wv * a.w;
            acc[4] += wv * b4.x; acc[5] += wv * b4.y;
            acc[6] += wv * b4.z; acc[7] += wv * b4.w;
        }
        __syncthreads();
    }

    // epilogue: bias + store + fused BN partial reduction
    float bv = bias[o];
    float ps = 0.f, pq = 0.f;
    size_t base = ((size_t)(b * 64 + o) * 128 + h) * 128 + w0 + pg * 8;
#pragma unroll
    for (int i = 0; i < 8; i++) {
        float v = acc[i] + bv;
        g_conv[base + i] = v;
        ps += v;
        pq += v * v;
    }
    // reduce across the 4 pixel-groups (threads o, o+64, o+128, o+192)
    red_s[t] = ps;
    red_q[t] = pq;
    __syncthreads();
    if (t < 64) {
        float s = red_s[t] + red_s[t + 64] + red_s[t + 128] + red_s[t + 192];
        float q = red_q[t] + red_q[t + 64] + red_q[t + 128] + red_q[t + 192];
        atomicAdd(&g_stats[t], s);
        atomicAdd(&g_stats[64 + t], q);
    }
}

// ---------------------------------------------------------------------------
// Finalize: per-channel affine + ReLU, float4 vectorized (HBM-bound).
__global__ __launch_bounds__(256) void finalize_kernel(
        const float* __restrict__ gamma, const float* __restrict__ beta,
        float* __restrict__ out) {
    __shared__ float s_scale[64], s_shift[64];
    if (threadIdx.x < 64) {
        const float invN = 1.f / 65536.f;   // B*H*W = 4*128*128
        int o = threadIdx.x;
        float mean = g_stats[o] * invN;
        float var  = g_stats[64 + o] * invN - mean * mean;
        float sc = rsqrtf(var + 1e-5f) * gamma[o];
        s_scale[o] = sc;
        s_shift[o] = beta[o] - mean * sc;
    }
    __syncthreads();
    const float4* cv = (const float4*)g_conv;
    float4* ov = (float4*)out;
    const size_t total4 = (size_t)4 * 64 * HW / 4;   // 1,048,576 float4s
    for (size_t i4 = (size_t)blockIdx.x * 256 + threadIdx.x; i4 < total4;
         i4 += (size_t)gridDim.x * 256) {
        int o = (int)((i4 >> 12) & 63);              // 4096 float4s per channel
        float sc = s_scale[o], sh = s_shift[o];
        float4 v = cv[i4];
        float4 r;
        r.x = fmaxf(v.x * sc + sh, 0.f);
        r.y = fmaxf(v.y * sc + sh, 0.f);
        r.z = fmaxf(v.z * sc + sh, 0.f);
        r.w = fmaxf(v.w * sc + sh, 0.f);
        ov[i4] = r;
    }
}

// ---------------------------------------------------------------------------
extern "C" void kernel_launch(void* const* d_in, const int* in_sizes, int n_in,
                              void* d_out, int out_size) {
    const float* x     = (const float*)d_in[0];
    const float* ow    = (const float*)d_in[1];
    const float* ob    = (const float*)d_in[2];
    const float* wgt   = (const float*)d_in[3];
    const float* bias  = (const float*)d_in[4];
    const float* gamma = (const float*)d_in[5];
    const float* beta  = (const float*)d_in[6];
    float* out = (float*)d_out;

    zero_stats_kernel<<<1, 128>>>();
    wt_transpose_kernel<<<144, 256>>>(wgt);
    offset_conv_kernel<<<dim3(8, 16, 4), 128>>>(x, ow, ob);
    deform_kernel<<<dim3(4, 128, 4), 256>>>(x, bias);
    finalize_kernel<<<2048, 256>>>(gamma, beta, out);
}

// round 9
// speedup vs baseline: 1.2194x; 1.2194x over previous
#include <cuda_runtime.h>

#define Hh 128
#define Ww 128
#define HW 16384
#define Bb 4
#define Cin 64
#define Cout 64

// scratch (device globals — no allocation)
__device__ float g_om[4 * 27 * HW];     // offset/mask conv output
__device__ float g_conv[4 * 64 * HW];   // deform conv output (pre-BN)
__device__ float g_wt[576 * 64];        // transposed deform weights [ck][o]
__device__ float g_stats[128];          // [0:64) sum, [64:128) sumsq

// ---------------------------------------------------------------------------
__global__ void zero_stats_kernel() {
    if (threadIdx.x < 128) g_stats[threadIdx.x] = 0.f;
}

// ---------------------------------------------------------------------------
// One-time weight transpose: g_wt[(c*9+k)*64 + o] = wgt[o*576 + c*9 + k]
__global__ __launch_bounds__(256) void wt_transpose_kernel(
        const float* __restrict__ wgt) {
    int idx = blockIdx.x * 256 + threadIdx.x;   // 36864 total
    if (idx < 576 * 64) {
        int o  = idx / 576;
        int ck = idx % 576;
        g_wt[ck * 64 + o] = wgt[idx];
    }
}

// ---------------------------------------------------------------------------
// Offset/mask conv (unchanged this round).
__global__ __launch_bounds__(128) void offset_conv_kernel(
        const float* __restrict__ x,
        const float* __restrict__ ow,
        const float* __restrict__ ob) {
    __shared__ __align__(16) float sw[32 * 9 * 28];   // 32.25 KB
    const int tx = threadIdx.x & 15;
    const int ty = threadIdx.x >> 4;
    const int w = blockIdx.x * 16 + tx;
    const int h = blockIdx.y * 8 + ty;
    const int b = blockIdx.z;

    float acc[28];
#pragma unroll
    for (int i = 0; i < 28; i++) acc[i] = 0.f;

    for (int cc = 0; cc < 64; cc += 32) {
        __syncthreads();
        for (int r = threadIdx.x; r < 288; r += 128) sw[r * 28 + 27] = 0.f;
        for (int j = threadIdx.x; j < 27 * 288; j += 128) {
            int oc = j / 288;
            int r  = j - oc * 288;               // cl*9 + tap
            sw[r * 28 + oc] = ow[oc * 576 + cc * 9 + r];
        }
        __syncthreads();
        for (int cl = 0; cl < 32; cl++) {
            const float* xb = x + ((size_t)(b * 64 + cc + cl)) * HW;
            float xv[9];
#pragma unroll
            for (int ky = 0; ky < 3; ky++)
#pragma unroll
                for (int kx = 0; kx < 3; kx++) {
                    int yy = h - 1 + ky, xx = w - 1 + kx;
                    xv[ky * 3 + kx] =
                        ((unsigned)yy < 128u && (unsigned)xx < 128u) ? xb[yy * 128 + xx] : 0.f;
                }
#pragma unroll
            for (int tap = 0; tap < 9; tap++) {
                float v = xv[tap];
                const float4* wp = (const float4*)&sw[(cl * 9 + tap) * 28];
#pragma unroll
                for (int q = 0; q < 7; q++) {
                    float4 wv = wp[q];
                    acc[q * 4 + 0] += v * wv.x;
                    acc[q * 4 + 1] += v * wv.y;
                    acc[q * 4 + 2] += v * wv.z;
                    acc[q * 4 + 3] += v * wv.w;
                }
            }
        }
    }
    size_t base = (size_t)b * 27 * HW + h * 128 + w;
#pragma unroll
    for (int oc = 0; oc < 27; oc++)
        g_om[base + (size_t)oc * HW] = acc[oc] + ob[oc];
}

// ---------------------------------------------------------------------------
// Deformable conv, v2: 64-pixel x 64-oc tile, 256 threads.
//   Precompute per (tap,pixel): packed clamped addr + folded corner weights.
//   Gather: 2 LDS + 4 LDG + 4 FFMA per item.
//   GEMM: each thread 2 oc x 8 px -> 16 FFMA / 4 LDS per ckl per warp.
//   Epilogue: float4 stores + fused BN partial sums.
__global__ __launch_bounds__(256) void deform_kernel(
        const float* __restrict__ x,
        const float* __restrict__ bias) {
    __shared__ int    s_pack[576];                      // 2.25 KB
    __shared__ __align__(16) float4 s_w4[576];          // 9 KB
    __shared__ __align__(16) float Vs[72 * 64];         // 18 KB
    __shared__ __align__(16) float ws[72 * 64];         // 18 KB
    __shared__ float red_s[256], red_q[256];            // 2 KB

    const int t  = threadIdx.x;
    const int b  = blockIdx.z;
    const int h  = blockIdx.y;
    const int w0 = blockIdx.x * 64;

    // phase 0: per-(tap, pixel) packed addr + folded corner weights
    for (int idx = t; idx < 576; idx += 256) {
        int p = idx & 63, k = idx >> 6;
        size_t omb = (size_t)b * 27 * HW + h * 128 + (w0 + p);
        float dy = g_om[omb + (size_t)(2 * k) * HW];
        float dx = g_om[omb + (size_t)(2 * k + 1) * HW];
        float ml = g_om[omb + (size_t)(18 + k) * HW];
        float ys = (float)(h - 1 + k / 3) + dy;
        float xs = (float)(w0 + p - 1 + (k % 3)) + dx;
        float y0f = floorf(ys), x0f = floorf(xs);
        int y0 = (int)y0f, x0 = (int)x0f;
        float fy = ys - y0f, fx = xs - x0f;
        float m = 1.f / (1.f + expf(-ml));
        bool vy0 = (unsigned)y0 < 128u, vy1 = (unsigned)(y0 + 1) < 128u;
        bool vx0 = (unsigned)x0 < 128u, vx1 = (unsigned)(x0 + 1) < 128u;
        int yc0 = min(max(y0, 0), 127),     xc0 = min(max(x0, 0), 127);
        int yc1 = min(max(y0 + 1, 0), 127), xc1 = min(max(x0 + 1, 0), 127);
        s_pack[idx] = (yc0 * 128 + xc0) | ((xc1 - xc0) << 14) | ((yc1 - yc0) << 15);
        float wy0 = 1.f - fy, wx0 = 1.f - fx;
        float4 wv;
        wv.x = wy0 * wx0 * m * (float)(vy0 && vx0);
        wv.y = wy0 * fx  * m * (float)(vy0 && vx1);
        wv.z = fy  * wx0 * m * (float)(vy1 && vx0);
        wv.w = fy  * fx  * m * (float)(vy1 && vx1);
        s_w4[idx] = wv;
    }
    __syncthreads();

    const int o  = t & 31;     // first output channel; second is o+32
    const int pg = t >> 5;     // warp id = pixel group (8 pixels)
    float acc1[8], acc2[8];
#pragma unroll
    for (int i = 0; i < 8; i++) { acc1[i] = 0.f; acc2[i] = 0.f; }

    for (int c0 = 0; c0 < 64; c0 += 8) {
        // stage weights: float4 copy of g_wt rows [c0*9 .. c0*9+72)
        {
            const float4* src = (const float4*)(g_wt + (size_t)c0 * 9 * 64);
            float4* dst = (float4*)ws;
            for (int j = t; j < 72 * 64 / 4; j += 256) dst[j] = src[j];
        }
        // gather V[ckl][p]: 4608 items, exactly 18 per thread
        for (int i = t; i < 72 * 64; i += 256) {
            int p   = i & 63;
            int ckl = i >> 6;
            int c   = c0 + ckl / 9;
            int ci  = (ckl % 9) * 64 + p;
            int pack = s_pack[ci];
            float4 wv = s_w4[ci];
            int a00 = pack & 16383;
            int dxi = (pack >> 14) & 1;
            int dyi = (pack >> 15) << 7;          // 0 or 128
            const float* xb = x + ((size_t)(b * 64 + c)) * HW;
            float v00 = xb[a00];
            float v01 = xb[a00 + dxi];
            float v10 = xb[a00 + dyi];
            float v11 = xb[a00 + dyi + dxi];
            Vs[ckl * 64 + p] = wv.x * v00 + wv.y * v01 + wv.z * v10 + wv.w * v11;
        }
        __syncthreads();
        // GEMM: 2 oc x 8 px per thread
#pragma unroll 4
        for (int ckl = 0; ckl < 72; ckl++) {
            float w1 = ws[ckl * 64 + o];
            float w2 = ws[ckl * 64 + o + 32];
            float4 va = *(const float4*)&Vs[ckl * 64 + pg * 8];
            float4 vb = *(const float4*)&Vs[ckl * 64 + pg * 8 + 4];
            acc1[0] += w1 * va.x;  acc1[1] += w1 * va.y;
            acc1[2] += w1 * va.z;  acc1[3] += w1 * va.w;
            acc1[4] += w1 * vb.x;  acc1[5] += w1 * vb.y;
            acc1[6] += w1 * vb.z;  acc1[7] += w1 * vb.w;
            acc2[0] += w2 * va.x;  acc2[1] += w2 * va.y;
            acc2[2] += w2 * va.z;  acc2[3] += w2 * va.w;
            acc2[4] += w2 * vb.x;  acc2[5] += w2 * vb.y;
            acc2[6] += w2 * vb.z;  acc2[7] += w2 * vb.w;
        }
        __syncthreads();
    }

    // epilogue: bias + vectorized store + fused BN partial sums
    float bv1 = bias[o], bv2 = bias[o + 32];
    float ps1 = 0.f, pq1 = 0.f, ps2 = 0.f, pq2 = 0.f;
    {
        size_t base1 = ((size_t)(b * 64 + o) * 128 + h) * 128 + w0 + pg * 8;
        size_t base2 = ((size_t)(b * 64 + o + 32) * 128 + h) * 128 + w0 + pg * 8;
        float4 r;
#pragma unroll
        for (int half = 0; half < 2; half++) {
            float v0 = acc1[half * 4 + 0] + bv1;
            float v1 = acc1[half * 4 + 1] + bv1;
            float v2 = acc1[half * 4 + 2] + bv1;
            float v3 = acc1[half * 4 + 3] + bv1;
            r.x = v0; r.y = v1; r.z = v2; r.w = v3;
            *(float4*)&g_conv[base1 + half * 4] = r;
            ps1 += v0 + v1 + v2 + v3;
            pq1 += v0 * v0 + v1 * v1 + v2 * v2 + v3 * v3;
            v0 = acc2[half * 4 + 0] + bv2;
            v1 = acc2[half * 4 + 1] + bv2;
            v2 = acc2[half * 4 + 2] + bv2;
            v3 = acc2[half * 4 + 3] + bv2;
            r.x = v0; r.y = v1; r.z = v2; r.w = v3;
            *(float4*)&g_conv[base2 + half * 4] = r;
            ps2 += v0 + v1 + v2 + v3;
            pq2 += v0 * v0 + v1 * v1 + v2 * v2 + v3 * v3;
        }
    }
    // channels 0..31
    red_s[t] = ps1; red_q[t] = pq1;
    __syncthreads();
    if (t < 32) {
        float s = 0.f, q = 0.f;
#pragma unroll
        for (int j = 0; j < 8; j++) { s += red_s[t + 32 * j]; q += red_q[t + 32 * j]; }
        atomicAdd(&g_stats[t], s);
        atomicAdd(&g_stats[64 + t], q);
    }
    __syncthreads();
    // channels 32..63
    red_s[t] = ps2; red_q[t] = pq2;
    __syncthreads();
    if (t < 32) {
        float s = 0.f, q = 0.f;
#pragma unroll
        for (int j = 0; j < 8; j++) { s += red_s[t + 32 * j]; q += red_q[t + 32 * j]; }
        atomicAdd(&g_stats[32 + t], s);
        atomicAdd(&g_stats[96 + t], q);
    }
}

// ---------------------------------------------------------------------------
// Finalize: per-channel affine + ReLU, float4 vectorized (HBM-bound).
__global__ __launch_bounds__(256) void finalize_kernel(
        const float* __restrict__ gamma, const float* __restrict__ beta,
        float* __restrict__ out) {
    __shared__ float s_scale[64], s_shift[64];
    if (threadIdx.x < 64) {
        const float invN = 1.f / 65536.f;   // B*H*W = 4*128*128
        int o = threadIdx.x;
        float mean = g_stats[o] * invN;
        float var  = g_stats[64 + o] * invN - mean * mean;
        float sc = rsqrtf(var + 1e-5f) * gamma[o];
        s_scale[o] = sc;
        s_shift[o] = beta[o] - mean * sc;
    }
    __syncthreads();
    const float4* cv = (const float4*)g_conv;
    float4* ov = (float4*)out;
    const size_t total4 = (size_t)4 * 64 * HW / 4;   // 1,048,576 float4s
    for (size_t i4 = (size_t)blockIdx.x * 256 + threadIdx.x; i4 < total4;
         i4 += (size_t)gridDim.x * 256) {
        int o = (int)((i4 >> 12) & 63);              // 4096 float4s per channel
        float sc = s_scale[o], sh = s_shift[o];
        float4 v = cv[i4];
        float4 r;
        r.x = fmaxf(v.x * sc + sh, 0.f);
        r.y = fmaxf(v.y * sc + sh, 0.f);
        r.z = fmaxf(v.z * sc + sh, 0.f);
        r.w = fmaxf(v.w * sc + sh, 0.f);
        ov[i4] = r;
    }
}

// ---------------------------------------------------------------------------
extern "C" void kernel_launch(void* const* d_in, const int* in_sizes, int n_in,
                              void* d_out, int out_size) {
    const float* x     = (const float*)d_in[0];
    const float* ow    = (const float*)d_in[1];
    const float* ob    = (const float*)d_in[2];
    const float* wgt   = (const float*)d_in[3];
    const float* bias  = (const float*)d_in[4];
    const float* gamma = (const float*)d_in[5];
    const float* beta  = (const float*)d_in[6];
    float* out = (float*)d_out;

    zero_stats_kernel<<<1, 128>>>();
    wt_transpose_kernel<<<144, 256>>>(wgt);
    offset_conv_kernel<<<dim3(8, 16, 4), 128>>>(x, ow, ob);
    deform_kernel<<<dim3(2, 128, 4), 256>>>(x, bias);
    finalize_kernel<<<2048, 256>>>(gamma, beta, out);
}